// round 15
// baseline (speedup 1.0000x reference)
#include <cuda_runtime.h>
#include <cuda_fp16.h>
#include <cstdint>

#define BB 64
#define NN 512
#define CC 1024
#define KC 64
#define NCH (CC/KC)          // 16 k-chunks

// Scratch (allocation-free rule: __device__ globals)
__device__ float g_S[(size_t)BB * NN * NN];      // 67 MB gram matrices
__device__ uint16_t g_mask16[BB * NN * 32];      // 2 MB per-lane adjacency bits
__device__ float g_rdeg[BB * NN];

// smem: 4 planes per buffer (A1,A2,B1,B2), 128 rows x 64 halves,
// padded row stride 144 B for conflict-free ldmatrix.
#define ROWB   144
#define TILE_B (128 * ROWB)          // 18432
#define BUF_B  (4 * TILE_B)          // 73728
#define SMEM_TOTAL (2 * BUF_B)       // 147456

#define NTHR 384                     // 8 MMA warps + 4 producer warps

// named barriers: FULL0=1, FULL1=2, EMPTY0=3, EMPTY1=4
#define BAR_SYNC(id)   asm volatile("bar.sync %0, %1;"   :: "r"(id), "n"(NTHR) : "memory")
#define BAR_ARRIVE(id) asm volatile("bar.arrive %0, %1;" :: "r"(id), "n"(NTHR) : "memory")

__device__ __forceinline__ uint32_t smem_u32(const void* p) {
    uint32_t a;
    asm("{ .reg .u64 t; cvta.to.shared.u64 t, %1; cvt.u32.u64 %0, t; }"
        : "=r"(a) : "l"(p));
    return a;
}
__device__ __forceinline__ void ldsm4(uint32_t& r0, uint32_t& r1,
                                      uint32_t& r2, uint32_t& r3, uint32_t a) {
    asm volatile("ldmatrix.sync.aligned.m8n8.x4.shared.b16 {%0,%1,%2,%3}, [%4];"
                 : "=r"(r0), "=r"(r1), "=r"(r2), "=r"(r3) : "r"(a));
}
__device__ __forceinline__ void mma16816(float* d, const uint32_t* a,
                                         uint32_t b0, uint32_t b1) {
    asm volatile(
        "mma.sync.aligned.m16n8k16.row.col.f32.f16.f16.f32 "
        "{%0,%1,%2,%3}, {%4,%5,%6,%7}, {%8,%9}, {%0,%1,%2,%3};"
        : "+f"(d[0]), "+f"(d[1]), "+f"(d[2]), "+f"(d[3])
        : "r"(a[0]), "r"(a[1]), "r"(a[2]), "r"(a[3]), "r"(b0), "r"(b1));
}

// ---------------------------------------------------------------------------
// Kernel A: warp-specialized HMMA split-fp16 GEMM (R6/R13 configuration =
// legacy-HMMA rate ceiling; 223.2-223.4 us reproduced across 4 runs).
// S = H1 H1^T + H1 H2^T + H2 H1^T, fp32 accumulation (exact to ~2^-22).
// ---------------------------------------------------------------------------
__global__ __launch_bounds__(NTHR, 1)
void gemm_ws_kernel(const float* __restrict__ X)
{
    extern __shared__ __align__(16) char smem[];
    const unsigned char ITm[10] = {0,0,0,0,1,1,1,2,2,3};
    const unsigned char JTm[10] = {0,1,2,3,1,2,3,2,3,3};
    const int it = ITm[blockIdx.x];
    const int jt = JTm[blockIdx.x];
    const int b  = blockIdx.y;
    const int rbase = it * 128;
    const int cbase = jt * 128;

    const int tid  = threadIdx.x;
    const int wid  = tid >> 5;
    const int lane = tid & 31;
    const uint32_t sb = smem_u32(smem);
    const float* __restrict__ Xb = X + (size_t)b * NN * CC;

    float acc[4][4][4];
    #pragma unroll
    for (int f = 0; f < 4; f++)
        #pragma unroll
        for (int n = 0; n < 4; n++)
            #pragma unroll
            for (int q = 0; q < 4; q++) acc[f][n][q] = 0.0f;

    if (wid >= 8) {
        // ---------------- producer warps ----------------
        const int ptid = tid - 256;          // 0..127
        #pragma unroll 1
        for (int c = 0; c < NCH; c++) {
            const int bs = c & 1;
            if (c >= 2) BAR_SYNC(3 + bs);    // wait EMPTY[bs]
            char* base = smem + bs * BUF_B;
            const int k0 = c * KC;
            #pragma unroll
            for (int i = 0; i < 32; i++) {
                int u  = i * 128 + ptid;     // 0..4095 16B-units
                int t  = u >> 11;            // 0=A rows, 1=B rows
                int r  = (u >> 4) & 127;
                int f4 = u & 15;
                int grow = (t ? cbase : rbase) + r;
                float4 v = *(const float4*)(Xb + (size_t)grow * CC + k0 + f4 * 4);
                __half2 a1 = __floats2half2_rn(v.x, v.y);
                __half2 b1 = __floats2half2_rn(v.z, v.w);
                float2 fa = __half22float2(a1);
                float2 fb = __half22float2(b1);
                __half2 a2 = __floats2half2_rn(v.x - fa.x, v.y - fa.y);
                __half2 b2 = __floats2half2_rn(v.z - fb.x, v.w - fb.y);
                int off = r * ROWB + f4 * 8;
                *(uint2*)(base + (t*2+0) * TILE_B + off) =
                    make_uint2(*(uint32_t*)&a1, *(uint32_t*)&b1);
                *(uint2*)(base + (t*2+1) * TILE_B + off) =
                    make_uint2(*(uint32_t*)&a2, *(uint32_t*)&b2);
            }
            BAR_ARRIVE(1 + bs);              // signal FULL[bs]
        }
    } else {
        // ---------------- MMA consumer warps ----------------
        const int wm = wid >> 2;             // 0..1  -> 64-row slab
        const int wn = wid & 3;              // 0..3  -> 32-col slab
        const int lrow = lane & 15;
        const int lcol = (lane >> 4) * 16;

        #pragma unroll 1
        for (int c = 0; c < NCH; c++) {
            const int bs = c & 1;
            BAR_SYNC(1 + bs);                // wait FULL[bs]

            const uint32_t tb  = sb + bs * BUF_B;
            const uint32_t pA1 = tb;
            const uint32_t pA2 = tb + TILE_B;
            const uint32_t pB1 = tb + 2 * TILE_B;
            const uint32_t pB2 = tb + 3 * TILE_B;

            #pragma unroll
            for (int ks = 0; ks < 4; ks++) {
                const int kb = ks * 32;      // 16 halves = 32 B
                uint32_t a1[4][4], a2[4][4], b1r[2][4], b2r[2][4];
                #pragma unroll
                for (int f = 0; f < 4; f++) {
                    uint32_t ad = (wm * 64 + f * 16 + lrow) * ROWB + lcol + kb;
                    ldsm4(a1[f][0], a1[f][1], a1[f][2], a1[f][3], pA1 + ad);
                    ldsm4(a2[f][0], a2[f][1], a2[f][2], a2[f][3], pA2 + ad);
                }
                #pragma unroll
                for (int g = 0; g < 2; g++) {
                    uint32_t ad = (wn * 32 + g * 16 + lrow) * ROWB + lcol + kb;
                    ldsm4(b1r[g][0], b1r[g][1], b1r[g][2], b1r[g][3], pB1 + ad);
                    ldsm4(b2r[g][0], b2r[g][1], b2r[g][2], b2r[g][3], pB2 + ad);
                }
                #pragma unroll
                for (int f = 0; f < 4; f++)
                    #pragma unroll
                    for (int g = 0; g < 2; g++)
                        #pragma unroll
                        for (int h = 0; h < 2; h++) {
                            float* d = acc[f][g*2+h];
                            mma16816(d, a1[f], b1r[g][0+h], b1r[g][2+h]);
                            mma16816(d, a1[f], b2r[g][0+h], b2r[g][2+h]);
                            mma16816(d, a2[f], b1r[g][0+h], b1r[g][2+h]);
                        }
            }
            BAR_ARRIVE(3 + bs);              // signal EMPTY[bs]
        }
    }

    __syncthreads();

    // ---- epilogue (consumer warps hold acc) ----
    float* __restrict__ Sb = g_S + (size_t)b * NN * NN;
    const int r0 = lane >> 2;
    const int c0 = (lane & 3) * 2;
    const int wm = wid >> 2;
    const int wn = wid & 3;

    if (wid < 8) {
        #pragma unroll
        for (int f = 0; f < 4; f++) {
            const int gr = rbase + wm * 64 + f * 16 + r0;
            #pragma unroll
            for (int n = 0; n < 4; n++) {
                const int gc = cbase + wn * 32 + n * 8 + c0;
                float* d = acc[f][n];
                *(float2*)&Sb[(size_t)gr * NN + gc]       = make_float2(d[0], d[1]);
                *(float2*)&Sb[(size_t)(gr + 8) * NN + gc] = make_float2(d[2], d[3]);
            }
        }
    }

    // mirror via smem transpose (coalesced both sides)
    if (jt > it) {
        float* st = (float*)smem;            // 128 x 129 floats
        if (wid < 8) {
            #pragma unroll
            for (int f = 0; f < 4; f++) {
                const int sr = wm * 64 + f * 16 + r0;
                #pragma unroll
                for (int n = 0; n < 4; n++) {
                    const int sc = wn * 32 + n * 8 + c0;
                    float* d = acc[f][n];
                    st[(size_t)sr * 129 + sc]           = d[0];
                    st[(size_t)sr * 129 + sc + 1]       = d[1];
                    st[(size_t)(sr + 8) * 129 + sc]     = d[2];
                    st[(size_t)(sr + 8) * 129 + sc + 1] = d[3];
                }
            }
        }
        __syncthreads();
        if (tid < 256) {
            const int mr = tid >> 1;
            const int hh = tid & 1;
            float* dst = Sb + (size_t)(cbase + mr) * NN + rbase + hh * 64;
            #pragma unroll
            for (int i = 0; i < 16; i++) {
                float4 v;
                v.x = st[(size_t)(hh * 64 + i * 4 + 0) * 129 + mr];
                v.y = st[(size_t)(hh * 64 + i * 4 + 1) * 129 + mr];
                v.z = st[(size_t)(hh * 64 + i * 4 + 2) * 129 + mr];
                v.w = st[(size_t)(hh * 64 + i * 4 + 3) * 129 + mr];
                *(float4*)(dst + i * 4) = v;
            }
        }
    }
}

// ---------------------------------------------------------------------------
// Kernel B: one WARP per row; exact 32nd-largest.
//  - prefix-skip radix between bounds t0 (min of lane maxes) and t2 (row
//    2nd-largest), resolving TWO bits per warp-collective: three tests
//    {1,2,3}<<bp counted into 10-bit packed fields -> ONE REDUX / 2 bits.
//  - per-lane top-4 fast counting with exact rare-path rescan.
//  - NO ballots: each lane packs its own 16 adjacency bits locally and
//    stores one uint16 (mask16[row*32+lane], bit 4*jj+q = col 4*(lane+32jj)+q).
// ---------------------------------------------------------------------------
__global__ __launch_bounds__(256)
void topk_threshold_kernel()
{
    const int row  = blockIdx.x * 8 + (threadIdx.x >> 5);
    const int lane = threadIdx.x & 31;
    const float* __restrict__ Sr = g_S + (size_t)row * NN;

    uint32_t u[16];
    const float4* S4 = (const float4*)Sr;
    #pragma unroll
    for (int j = 0; j < 4; j++) {
        float4 t = S4[lane + 32 * j];
        float f[4] = {t.x, t.y, t.z, t.w};
        #pragma unroll
        for (int q = 0; q < 4; q++) {
            uint32_t s = __float_as_uint(f[q]);
            u[4*j+q] = (s & 0x80000000u) ? ~s : (s | 0x80000000u);
        }
    }

    // per-lane top-4 (descending): s0 >= s1 >= s2 >= s3
    uint32_t s0 = 0, s1 = 0, s2 = 0, s3 = 0;
    #pragma unroll
    for (int j = 0; j < 16; j++) {
        uint32_t v = u[j], t;
        t = max(s0, v); v = min(s0, v); s0 = t;
        t = max(s1, v); v = min(s1, v); s1 = t;
        t = max(s2, v); v = min(s2, v); s2 = t;
        s3 = max(s3, v);
    }

    const uint32_t t0   = __reduce_min_sync(0xffffffffu, s0);  // lower bound
    const uint32_t tmax = __reduce_max_sync(0xffffffffu, s0);  // row max
    const uint32_t t2 = __reduce_max_sync(0xffffffffu, (s0 == tmax) ? s1 : s0);

    uint32_t thr;
    if (t0 >= t2) {
        thr = t0;
    } else {
        const int b0 = 31 - __clz(t0 ^ t2);
        const uint32_t low = (uint32_t)(((uint64_t)2 << b0) - 1u);
        thr = t0 & ~low;               // common prefix, unknown bits zero
        #pragma unroll 1
        for (int bp = b0 & ~1; bp >= 0; bp -= 2) {
            const uint32_t t01 = thr | (1u << bp);
            const uint32_t t10 = thr | (2u << bp);
            const uint32_t t11 = thr | (3u << bp);
            uint32_t cl;
            int c01 = (int)(s0 >= t01) + (int)(s1 >= t01)
                    + (int)(s2 >= t01) + (int)(s3 >= t01);
            if (c01 == 4) {            // lane may hold >4 above t01: exact rescan
                int a = 0, b = 0, cc = 0;
                #pragma unroll
                for (int j = 0; j < 16; j++) {
                    a  += (u[j] >= t01);
                    b  += (u[j] >= t10);
                    cc += (u[j] >= t11);
                }
                cl = (uint32_t)a + ((uint32_t)b << 10) + ((uint32_t)cc << 20);
            } else {
                int c10 = (int)(s0 >= t10) + (int)(s1 >= t10)
                        + (int)(s2 >= t10) + (int)(s3 >= t10);
                int c11 = (int)(s0 >= t11) + (int)(s1 >= t11)
                        + (int)(s2 >= t11) + (int)(s3 >= t11);
                cl = (uint32_t)c01 + ((uint32_t)c10 << 10) + ((uint32_t)c11 << 20);
            }
            // fields <= 512 each -> no carry across 10-bit fields
            const uint32_t r = __reduce_add_sync(0xffffffffu, cl);
            const uint32_t n01 = r & 0x3FFu;
            const uint32_t n10 = (r >> 10) & 0x3FFu;
            const uint32_t n11 = r >> 20;
            if      (n11 >= 32) thr = t11;
            else if (n10 >= 32) thr = t10;
            else if (n01 >= 32) thr = t01;
        }
    }

    // per-lane adjacency bits (no ballot) + degree (one REDUX)
    uint32_t lm = 0;
    #pragma unroll
    for (int j = 0; j < 16; j++) lm |= (uint32_t)(u[j] >= thr) << j;
    int cnt = __popc(lm);
    cnt = __reduce_add_sync(0xffffffffu, cnt);

    g_mask16[row * 32 + lane] = (uint16_t)lm;
    if (lane == 0) g_rdeg[row] = rsqrtf((float)cnt);
}

// ---------------------------------------------------------------------------
// Kernel C: out[b,i,j] = maskbit ? rdeg_i * rdeg_j : 0   (write-bound)
// Thread f (0..127) of a row reads mask16[row*32 + f%32]; its 4 output
// columns 4f+q use bits 4*(f>>5)+q.
// ---------------------------------------------------------------------------
__global__ __launch_bounds__(256)
void normalize_kernel(float* __restrict__ out)
{
    const size_t idx = (size_t)blockIdx.x * blockDim.x + threadIdx.x;
    const int f   = (int)(idx & 127);
    const int row = (int)(idx >> 7);
    const int b   = row >> 9;

    const uint32_t mw = (uint32_t)g_mask16[row * 32 + (f & 31)];
    const int bb = (f >> 5) * 4;

    const float ri = g_rdeg[row];
    const float* rj = g_rdeg + b * NN + f * 4;

    float4 o;
    o.x = ((mw >> (bb + 0)) & 1u) ? ri * rj[0] : 0.0f;
    o.y = ((mw >> (bb + 1)) & 1u) ? ri * rj[1] : 0.0f;
    o.z = ((mw >> (bb + 2)) & 1u) ? ri * rj[2] : 0.0f;
    o.w = ((mw >> (bb + 3)) & 1u) ? ri * rj[3] : 0.0f;
    ((float4*)out)[idx] = o;
}

// ---------------------------------------------------------------------------
extern "C" void kernel_launch(void* const* d_in, const int* in_sizes, int n_in,
                              void* d_out, int out_size)
{
    const float* x = (const float*)d_in[0];
    float* out = (float*)d_out;

    cudaFuncSetAttribute(gemm_ws_kernel,
                         cudaFuncAttributeMaxDynamicSharedMemorySize, SMEM_TOTAL);

    dim3 gGemm(10, BB);
    gemm_ws_kernel<<<gGemm, NTHR, SMEM_TOTAL>>>(x);

    topk_threshold_kernel<<<BB * NN / 8, 256>>>();

    const int n4 = BB * NN * NN / 4;
    normalize_kernel<<<n4 / 256, 256>>>(out);
}

// round 16
// speedup vs baseline: 1.1305x; 1.1305x over previous
#include <cuda_runtime.h>
#include <cuda_fp16.h>
#include <cstdint>

#define BB 64
#define NN 512
#define CC 1024
#define KC 64
#define NCH (CC/KC)          // 16 k-chunks

// Scratch (allocation-free rule: __device__ globals)
__device__ float g_S[(size_t)BB * NN * NN];      // 67 MB gram matrices
__device__ uint32_t g_mask[BB * NN * 16];        // 2 MB adjacency ballots
__device__ float g_rdeg[BB * NN];

// smem: 4 planes per buffer (A1,A2,B1,B2), 128 rows x 64 halves,
// padded row stride 144 B for conflict-free ldmatrix.
#define ROWB   144
#define TILE_B (128 * ROWB)          // 18432
#define BUF_B  (4 * TILE_B)          // 73728
#define SMEM_TOTAL (2 * BUF_B)       // 147456

#define NTHR 384                     // 8 MMA warps + 4 producer warps

// named barriers: FULL0=1, FULL1=2, EMPTY0=3, EMPTY1=4
#define BAR_SYNC(id)   asm volatile("bar.sync %0, %1;"   :: "r"(id), "n"(NTHR) : "memory")
#define BAR_ARRIVE(id) asm volatile("bar.arrive %0, %1;" :: "r"(id), "n"(NTHR) : "memory")

__device__ __forceinline__ uint32_t smem_u32(const void* p) {
    uint32_t a;
    asm("{ .reg .u64 t; cvta.to.shared.u64 t, %1; cvt.u32.u64 %0, t; }"
        : "=r"(a) : "l"(p));
    return a;
}
__device__ __forceinline__ void ldsm4(uint32_t& r0, uint32_t& r1,
                                      uint32_t& r2, uint32_t& r3, uint32_t a) {
    asm volatile("ldmatrix.sync.aligned.m8n8.x4.shared.b16 {%0,%1,%2,%3}, [%4];"
                 : "=r"(r0), "=r"(r1), "=r"(r2), "=r"(r3) : "r"(a));
}
__device__ __forceinline__ void mma16816(float* d, const uint32_t* a,
                                         uint32_t b0, uint32_t b1) {
    asm volatile(
        "mma.sync.aligned.m16n8k16.row.col.f32.f16.f16.f32 "
        "{%0,%1,%2,%3}, {%4,%5,%6,%7}, {%8,%9}, {%0,%1,%2,%3};"
        : "+f"(d[0]), "+f"(d[1]), "+f"(d[2]), "+f"(d[3])
        : "r"(a[0]), "r"(a[1]), "r"(a[2]), "r"(a[3]), "r"(b0), "r"(b1));
}

// ---------------------------------------------------------------------------
// Kernel A: warp-specialized HMMA split-fp16 GEMM (R6/R13 configuration =
// legacy-HMMA rate ceiling; 223.2-223.7 us reproduced across 5 runs).
// S = H1 H1^T + H1 H2^T + H2 H1^T, fp32 accumulation (exact to ~2^-22).
// ---------------------------------------------------------------------------
__global__ __launch_bounds__(NTHR, 1)
void gemm_ws_kernel(const float* __restrict__ X)
{
    extern __shared__ __align__(16) char smem[];
    const unsigned char ITm[10] = {0,0,0,0,1,1,1,2,2,3};
    const unsigned char JTm[10] = {0,1,2,3,1,2,3,2,3,3};
    const int it = ITm[blockIdx.x];
    const int jt = JTm[blockIdx.x];
    const int b  = blockIdx.y;
    const int rbase = it * 128;
    const int cbase = jt * 128;

    const int tid  = threadIdx.x;
    const int wid  = tid >> 5;
    const int lane = tid & 31;
    const uint32_t sb = smem_u32(smem);
    const float* __restrict__ Xb = X + (size_t)b * NN * CC;

    float acc[4][4][4];
    #pragma unroll
    for (int f = 0; f < 4; f++)
        #pragma unroll
        for (int n = 0; n < 4; n++)
            #pragma unroll
            for (int q = 0; q < 4; q++) acc[f][n][q] = 0.0f;

    if (wid >= 8) {
        // ---------------- producer warps ----------------
        const int ptid = tid - 256;          // 0..127
        #pragma unroll 1
        for (int c = 0; c < NCH; c++) {
            const int bs = c & 1;
            if (c >= 2) BAR_SYNC(3 + bs);    // wait EMPTY[bs]
            char* base = smem + bs * BUF_B;
            const int k0 = c * KC;
            #pragma unroll
            for (int i = 0; i < 32; i++) {
                int u  = i * 128 + ptid;     // 0..4095 16B-units
                int t  = u >> 11;            // 0=A rows, 1=B rows
                int r  = (u >> 4) & 127;
                int f4 = u & 15;
                int grow = (t ? cbase : rbase) + r;
                float4 v = *(const float4*)(Xb + (size_t)grow * CC + k0 + f4 * 4);
                __half2 a1 = __floats2half2_rn(v.x, v.y);
                __half2 b1 = __floats2half2_rn(v.z, v.w);
                float2 fa = __half22float2(a1);
                float2 fb = __half22float2(b1);
                __half2 a2 = __floats2half2_rn(v.x - fa.x, v.y - fa.y);
                __half2 b2 = __floats2half2_rn(v.z - fb.x, v.w - fb.y);
                int off = r * ROWB + f4 * 8;
                *(uint2*)(base + (t*2+0) * TILE_B + off) =
                    make_uint2(*(uint32_t*)&a1, *(uint32_t*)&b1);
                *(uint2*)(base + (t*2+1) * TILE_B + off) =
                    make_uint2(*(uint32_t*)&a2, *(uint32_t*)&b2);
            }
            BAR_ARRIVE(1 + bs);              // signal FULL[bs]
        }
    } else {
        // ---------------- MMA consumer warps ----------------
        const int wm = wid >> 2;             // 0..1  -> 64-row slab
        const int wn = wid & 3;              // 0..3  -> 32-col slab
        const int lrow = lane & 15;
        const int lcol = (lane >> 4) * 16;

        #pragma unroll 1
        for (int c = 0; c < NCH; c++) {
            const int bs = c & 1;
            BAR_SYNC(1 + bs);                // wait FULL[bs]

            const uint32_t tb  = sb + bs * BUF_B;
            const uint32_t pA1 = tb;
            const uint32_t pA2 = tb + TILE_B;
            const uint32_t pB1 = tb + 2 * TILE_B;
            const uint32_t pB2 = tb + 3 * TILE_B;

            #pragma unroll
            for (int ks = 0; ks < 4; ks++) {
                const int kb = ks * 32;      // 16 halves = 32 B
                uint32_t a1[4][4], a2[4][4], b1r[2][4], b2r[2][4];
                #pragma unroll
                for (int f = 0; f < 4; f++) {
                    uint32_t ad = (wm * 64 + f * 16 + lrow) * ROWB + lcol + kb;
                    ldsm4(a1[f][0], a1[f][1], a1[f][2], a1[f][3], pA1 + ad);
                    ldsm4(a2[f][0], a2[f][1], a2[f][2], a2[f][3], pA2 + ad);
                }
                #pragma unroll
                for (int g = 0; g < 2; g++) {
                    uint32_t ad = (wn * 32 + g * 16 + lrow) * ROWB + lcol + kb;
                    ldsm4(b1r[g][0], b1r[g][1], b1r[g][2], b1r[g][3], pB1 + ad);
                    ldsm4(b2r[g][0], b2r[g][1], b2r[g][2], b2r[g][3], pB2 + ad);
                }
                #pragma unroll
                for (int f = 0; f < 4; f++)
                    #pragma unroll
                    for (int g = 0; g < 2; g++)
                        #pragma unroll
                        for (int h = 0; h < 2; h++) {
                            float* d = acc[f][g*2+h];
                            mma16816(d, a1[f], b1r[g][0+h], b1r[g][2+h]);
                            mma16816(d, a1[f], b2r[g][0+h], b2r[g][2+h]);
                            mma16816(d, a2[f], b1r[g][0+h], b1r[g][2+h]);
                        }
            }
            BAR_ARRIVE(3 + bs);              // signal EMPTY[bs]
        }
    }

    __syncthreads();

    // ---- epilogue (consumer warps hold acc) ----
    float* __restrict__ Sb = g_S + (size_t)b * NN * NN;
    const int r0 = lane >> 2;
    const int c0 = (lane & 3) * 2;
    const int wm = wid >> 2;
    const int wn = wid & 3;

    if (wid < 8) {
        #pragma unroll
        for (int f = 0; f < 4; f++) {
            const int gr = rbase + wm * 64 + f * 16 + r0;
            #pragma unroll
            for (int n = 0; n < 4; n++) {
                const int gc = cbase + wn * 32 + n * 8 + c0;
                float* d = acc[f][n];
                *(float2*)&Sb[(size_t)gr * NN + gc]       = make_float2(d[0], d[1]);
                *(float2*)&Sb[(size_t)(gr + 8) * NN + gc] = make_float2(d[2], d[3]);
            }
        }
    }

    // mirror via smem transpose (coalesced both sides)
    if (jt > it) {
        float* st = (float*)smem;            // 128 x 129 floats
        if (wid < 8) {
            #pragma unroll
            for (int f = 0; f < 4; f++) {
                const int sr = wm * 64 + f * 16 + r0;
                #pragma unroll
                for (int n = 0; n < 4; n++) {
                    const int sc = wn * 32 + n * 8 + c0;
                    float* d = acc[f][n];
                    st[(size_t)sr * 129 + sc]           = d[0];
                    st[(size_t)sr * 129 + sc + 1]       = d[1];
                    st[(size_t)(sr + 8) * 129 + sc]     = d[2];
                    st[(size_t)(sr + 8) * 129 + sc + 1] = d[3];
                }
            }
        }
        __syncthreads();
        if (tid < 256) {
            const int mr = tid >> 1;
            const int hh = tid & 1;
            float* dst = Sb + (size_t)(cbase + mr) * NN + rbase + hh * 64;
            #pragma unroll
            for (int i = 0; i < 16; i++) {
                float4 v;
                v.x = st[(size_t)(hh * 64 + i * 4 + 0) * 129 + mr];
                v.y = st[(size_t)(hh * 64 + i * 4 + 1) * 129 + mr];
                v.z = st[(size_t)(hh * 64 + i * 4 + 2) * 129 + mr];
                v.w = st[(size_t)(hh * 64 + i * 4 + 3) * 129 + mr];
                *(float4*)(dst + i * 4) = v;
            }
        }
    }
}

// ---------------------------------------------------------------------------
// Kernel B: one WARP per row; exact 32nd-largest via prefix-skip 1-bit radix
// with per-lane top-4 fast counting (R13) + EARLY EXIT: the moment the
// count pins to exactly 32, thr = reduce-min of the 32 candidates -> done.
// Emits adjacency ballots (16 words/row) + rdeg.
// ---------------------------------------------------------------------------
__global__ __launch_bounds__(256)
void topk_threshold_kernel()
{
    const int row  = blockIdx.x * 8 + (threadIdx.x >> 5);
    const int lane = threadIdx.x & 31;
    const float* __restrict__ Sr = g_S + (size_t)row * NN;

    uint32_t u[16];
    const float4* S4 = (const float4*)Sr;
    #pragma unroll
    for (int j = 0; j < 4; j++) {
        float4 t = S4[lane + 32 * j];
        float f[4] = {t.x, t.y, t.z, t.w};
        #pragma unroll
        for (int q = 0; q < 4; q++) {
            uint32_t s = __float_as_uint(f[q]);
            u[4*j+q] = (s & 0x80000000u) ? ~s : (s | 0x80000000u);
        }
    }

    // per-lane top-4 (descending): s0 >= s1 >= s2 >= s3
    uint32_t s0 = 0, s1 = 0, s2 = 0, s3 = 0;
    #pragma unroll
    for (int j = 0; j < 16; j++) {
        uint32_t v = u[j], t;
        t = max(s0, v); v = min(s0, v); s0 = t;
        t = max(s1, v); v = min(s1, v); s1 = t;
        t = max(s2, v); v = min(s2, v); s2 = t;
        s3 = max(s3, v);
    }

    const uint32_t t0   = __reduce_min_sync(0xffffffffu, s0);  // lower bound
    const uint32_t tmax = __reduce_max_sync(0xffffffffu, s0);  // row max
    const uint32_t t2 = __reduce_max_sync(0xffffffffu, (s0 == tmax) ? s1 : s0);

    uint32_t thr;
    if (t0 >= t2) {
        thr = t0;
    } else {
        const int b0 = 31 - __clz(t0 ^ t2);
        const uint32_t low = (uint32_t)(((uint64_t)2 << b0) - 1u);
        thr = t0 & ~low;               // common prefix, unknown bits zero
        #pragma unroll 1
        for (int bit = b0; bit >= 0; bit--) {
            const uint32_t test = thr | (1u << bit);
            int c = (int)(s0 >= test) + (int)(s1 >= test)
                  + (int)(s2 >= test) + (int)(s3 >= test);
            if (c == 4) {              // lane may hold >4 above test: exact rescan
                int cf = 0;
                #pragma unroll
                for (int j = 0; j < 16; j++) cf += (u[j] >= test);
                c = cf;
            }
            c = __reduce_add_sync(0xffffffffu, c);
            if (c == 32) {
                // candidates == exact top-32; thr = min of them. Done.
                uint32_t lmin = 0xffffffffu;
                #pragma unroll
                for (int j = 0; j < 16; j++)
                    lmin = min(lmin, (u[j] >= test) ? u[j] : 0xffffffffu);
                thr = __reduce_min_sync(0xffffffffu, lmin);
                break;
            }
            if (c > 32) thr = test;
        }
    }

    // adjacency ballots + degree
    uint32_t m[16];
    int cnt = 0;
    #pragma unroll
    for (int j = 0; j < 16; j++) {
        m[j] = __ballot_sync(0xffffffffu, u[j] >= thr);
        cnt += __popc(m[j]);
    }

    uint32_t* __restrict__ Mr = g_mask + row * 16;
    if (lane < 16) Mr[lane] = m[lane];
    if (lane == 0) g_rdeg[row] = rsqrtf((float)cnt);
}

// ---------------------------------------------------------------------------
// Kernel C: out[b,i,j] = mask[b,i,j] ? rdeg_i * rdeg_j : 0   (write-bound)
// ---------------------------------------------------------------------------
__global__ __launch_bounds__(256)
void normalize_kernel(float* __restrict__ out)
{
    const size_t idx = (size_t)blockIdx.x * blockDim.x + threadIdx.x;
    const int f   = (int)(idx & 127);
    const int row = (int)(idx >> 7);
    const int b   = row >> 9;

    const int j    = f >> 5;
    const int lane = f & 31;

    const uint4 mw = *(const uint4*)(g_mask + row * 16 + 4 * j);
    const float ri = g_rdeg[row];
    const float* rj = g_rdeg + b * NN + f * 4;

    float4 o;
    o.x = ((mw.x >> lane) & 1u) ? ri * rj[0] : 0.0f;
    o.y = ((mw.y >> lane) & 1u) ? ri * rj[1] : 0.0f;
    o.z = ((mw.z >> lane) & 1u) ? ri * rj[2] : 0.0f;
    o.w = ((mw.w >> lane) & 1u) ? ri * rj[3] : 0.0f;
    ((float4*)out)[idx] = o;
}

// ---------------------------------------------------------------------------
extern "C" void kernel_launch(void* const* d_in, const int* in_sizes, int n_in,
                              void* d_out, int out_size)
{
    const float* x = (const float*)d_in[0];
    float* out = (float*)d_out;

    cudaFuncSetAttribute(gemm_ws_kernel,
                         cudaFuncAttributeMaxDynamicSharedMemorySize, SMEM_TOTAL);

    dim3 gGemm(10, BB);
    gemm_ws_kernel<<<gGemm, NTHR, SMEM_TOTAL>>>(x);

    topk_threshold_kernel<<<BB * NN / 8, 256>>>();

    const int n4 = BB * NN * NN / 4;
    normalize_kernel<<<n4 / 256, 256>>>(out);
}